// round 15
// baseline (speedup 1.0000x reference)
#include <cuda_runtime.h>
#include <cuda_bf16.h>
#include <cstdint>

// Gather: out[i, y, x, c] = logits[i * N_SP + segments[i, y, x], c]
//   logits:   [16*512, 5] fp32 (10 KB per image, TMA-staged once per block)
//   segments: [16, 512, 512] int32 (TMA-staged, 5 single-use buffers)
//   out:      [16, 512, 512, 5] fp32
//
// R15 = R14 (single-wave persistent blocks, balanced 19/18-unit split, all
// TMA loads issued up-front, zero in-loop block barriers) + ILP: the 4 units
// of each chunk are fully unrolled so their seg LDS / gather LDS / STG chains
// interleave (R14's unroll-1 loop had regs=19 and a serial ~70cyc chain per
// unit; R9 showed regs=32 full unrolling sustains issue).

#define N_IMG 16
#define SIZE  512
#define N_SP  512
#define WAY   5
#define PIX_PER_IMG    (SIZE * SIZE)            // 262144
#define VEC_PER_IMG    (PIX_PER_IMG * WAY / 4)  // 327680 float4
#define LOGITS_PER_IMG (N_SP * WAY)             // 2560 floats = 10240 B

#define THREADS 320
#define BLOCKS_PER_IMG 55                       // 880 blocks <= 148*6 = 888
#define UNIT_PIX   256
#define UNIT_VEC   320
#define UNITS_PER_CHUNK 4
#define MAX_CHUNKS 5

#define LOGITS_BYTES (LOGITS_PER_IMG * 4)       // 10240
#define CHUNK_PIX   (UNITS_PER_CHUNK * UNIT_PIX) // 1024
#define CHUNK_BYTES (CHUNK_PIX * 4)              // 4096

// 1024 units = 55*18 + 34 -> first 34 blocks get 19 units, rest 18
#define BIG_BLOCKS 34

__device__ __forceinline__ uint32_t smem_u32(const void* p) {
    uint32_t a;
    asm("{ .reg .u64 t; cvta.to.shared.u64 t, %1; cvt.u32.u64 %0, t; }"
        : "=r"(a) : "l"(p));
    return a;
}

__device__ __forceinline__ void mbar_wait0(uint32_t mb) {
    uint32_t done;
    asm volatile(
        "{\n\t"
        ".reg .pred p;\n\t"
        "mbarrier.try_wait.parity.acquire.cta.shared::cta.b64 p, [%1], 0;\n\t"
        "selp.b32 %0, 1, 0, p;\n\t"
        "}" : "=r"(done) : "r"(mb) : "memory");
    if (!done) {
        asm volatile(
            "{\n\t"
            ".reg .pred P1;\n\t"
            "WL_%=:\n\t"
            "mbarrier.try_wait.parity.acquire.cta.shared::cta.b64 P1, [%0], 0, 0x989680;\n\t"
            "@P1 bra.uni WD_%=;\n\t"
            "bra.uni WL_%=;\n\t"
            "WD_%=:\n\t"
            "}" :: "r"(mb) : "memory");
    }
}

__global__ void __launch_bounds__(THREADS, 6)
sp_gather_kernel15(const float* __restrict__ logits,
                   const int* __restrict__ seg,
                   float4* __restrict__ out)
{
    __shared__ __align__(16) float    s_logits[LOGITS_PER_IMG];
    __shared__ __align__(16) int      s_seg[MAX_CHUNKS][CHUNK_PIX];
    __shared__ __align__(8)  uint64_t s_mbar[MAX_CHUNKS];

    const int img = blockIdx.y;
    const int blk = blockIdx.x;          // 0..54
    const int tid = threadIdx.x;

    const int big    = (blk < BIG_BLOCKS);
    const int ucount = 18 + big;                               // 18 or 19
    const int ustart = 18 * blk + (big ? blk : BIG_BLOCKS);

    if (tid == 0) {
#pragma unroll
        for (int c = 0; c < MAX_CHUNKS; ++c) {
            uint32_t mb = smem_u32(&s_mbar[c]);
            asm volatile("mbarrier.init.shared.b64 [%0], 1;" :: "r"(mb) : "memory");
        }
    }
    __syncthreads();   // the only block-wide barrier

    const int* seg_img = seg + (size_t)img * PIX_PER_IMG;

    // Issue ALL TMA loads up-front (engine-queued).
    if (tid == 0) {
        {   // chunk 0's barrier also covers the logits copy
            uint32_t mb = smem_u32(&s_mbar[0]);
            uint32_t tx = LOGITS_BYTES + CHUNK_BYTES;
            asm volatile("mbarrier.arrive.expect_tx.shared.b64 _, [%0], %1;"
                         :: "r"(mb), "r"(tx) : "memory");
            uint32_t dl = smem_u32(s_logits);
            const void* sl = logits + (size_t)img * LOGITS_PER_IMG;
            asm volatile(
                "cp.async.bulk.shared::cta.global.mbarrier::complete_tx::bytes "
                "[%0], [%1], %2, [%3];"
                :: "r"(dl), "l"(sl), "n"(LOGITS_BYTES), "r"(mb) : "memory");
            uint32_t ds = smem_u32(&s_seg[0][0]);
            const void* ss = seg_img + (size_t)ustart * UNIT_PIX;
            asm volatile(
                "cp.async.bulk.shared::cta.global.mbarrier::complete_tx::bytes "
                "[%0], [%1], %2, [%3];"
                :: "r"(ds), "l"(ss), "n"(CHUNK_BYTES), "r"(mb) : "memory");
        }
#pragma unroll
        for (int c = 1; c < MAX_CHUNKS; ++c) {
            int uc = ucount - c * UNITS_PER_CHUNK;
            if (uc <= 0) break;
            if (uc > UNITS_PER_CHUNK) uc = UNITS_PER_CHUNK;
            uint32_t bytes = uc * UNIT_PIX * 4;
            uint32_t mb = smem_u32(&s_mbar[c]);
            asm volatile("mbarrier.arrive.expect_tx.shared.b64 _, [%0], %1;"
                         :: "r"(mb), "r"(bytes) : "memory");
            uint32_t ds = smem_u32(&s_seg[c][0]);
            const void* ss = seg_img + (size_t)(ustart + c * UNITS_PER_CHUNK) * UNIT_PIX;
            asm volatile(
                "cp.async.bulk.shared::cta.global.mbarrier::complete_tx::bytes "
                "[%0], [%1], %2, [%3];"
                :: "r"(ds), "l"(ss), "r"(bytes), "r"(mb) : "memory");
        }
    }

    // Per-thread constants.
    const int floc = tid << 2;            // 0..1276 within a unit
    const int p0   = floc / 5;            // 0..255
    const int r    = floc - 5 * p0;       // constant channel remainder 0..4
    const int m    = 5 - r;
    const bool need_s1 = (r >= 2);        // in-unit (max p0 needing s1 is 254)

    float4* out_units = out + (size_t)img * VEC_PER_IMG
                            + (size_t)ustart * UNIT_VEC + tid;

    const int full_chunks = ucount / UNITS_PER_CHUNK;           // 4
    const int rem = ucount - full_chunks * UNITS_PER_CHUNK;     // 2 or 3

#pragma unroll 1
    for (int c = 0; c < full_chunks; ++c) {
        mbar_wait0(smem_u32(&s_mbar[c]));
#pragma unroll
        for (int uu = 0; uu < UNITS_PER_CHUNK; ++uu) {
            const int* sseg = &s_seg[c][uu * UNIT_PIX];
            int b0 = sseg[p0] * WAY + r;
            int b1 = need_s1 ? (sseg[p0 + 1] * WAY + r - 5) : 0;

            float v0 = s_logits[((0 < m) ? b0 : b1) + 0];
            float v1 = s_logits[((1 < m) ? b0 : b1) + 1];
            float v2 = s_logits[((2 < m) ? b0 : b1) + 2];
            float v3 = s_logits[((3 < m) ? b0 : b1) + 3];

            out_units[(size_t)(c * UNITS_PER_CHUNK + uu) * UNIT_VEC] =
                make_float4(v0, v1, v2, v3);
        }
    }

    // Tail chunk (2 or 3 units).
    {
        const int c = full_chunks;
        mbar_wait0(smem_u32(&s_mbar[c]));
#pragma unroll 1
        for (int uu = 0; uu < rem; ++uu) {
            const int* sseg = &s_seg[c][uu * UNIT_PIX];
            int b0 = sseg[p0] * WAY + r;
            int b1 = need_s1 ? (sseg[p0 + 1] * WAY + r - 5) : 0;

            float v0 = s_logits[((0 < m) ? b0 : b1) + 0];
            float v1 = s_logits[((1 < m) ? b0 : b1) + 1];
            float v2 = s_logits[((2 < m) ? b0 : b1) + 2];
            float v3 = s_logits[((3 < m) ? b0 : b1) + 3];

            out_units[(size_t)(c * UNITS_PER_CHUNK + uu) * UNIT_VEC] =
                make_float4(v0, v1, v2, v3);
        }
    }
}

extern "C" void kernel_launch(void* const* d_in, const int* in_sizes, int n_in,
                              void* d_out, int out_size)
{
    const float* logits = (const float*)d_in[0];
    const int*   seg    = (const int*)d_in[1];
    float4*      out    = (float4*)d_out;

    dim3 grid(BLOCKS_PER_IMG, N_IMG);
    sp_gather_kernel15<<<grid, THREADS>>>(logits, seg, out);
}